// round 10
// baseline (speedup 1.0000x reference)
#include <cuda_runtime.h>
#include <cuda_bf16.h>
#include <cstdint>

#define MAX_NODES 100000
#define MAX_EDGES 625000
#define F 128
#define SSTRIDE 136   // padded bf16 row stride -> conflict-free fragment LDS
#define SCAN_B 512    // nodes per scan block
#define GTILE 128     // rows per tile (persistent loop)

__device__ int g_cnt[MAX_NODES];
__device__ int g_base[MAX_NODES];
__device__ int g_cursor[MAX_NODES];
__device__ int g_sorted[MAX_EDGES];
__device__ int g_bsums[256];
__device__ int g_ticket;
// pre-split weight planes (hi/lo bf16), filled once per launch
__device__ __align__(16) __nv_bfloat16 g_whi[F * F];
__device__ __align__(16) __nv_bfloat16 g_wlo[F * F];
__device__ __align__(16) __nv_bfloat16 g_bhi[F * F];
__device__ __align__(16) __nv_bfloat16 g_blo[F * F];

// ---------------------------------------------------------------------------
// P1: zero histogram + ticket + pre-split W/B into bf16 hi/lo planes
// ---------------------------------------------------------------------------
__global__ void p1_zero_conv(const float* __restrict__ W,
                             const float* __restrict__ B, int N) {
    int i = blockIdx.x * blockDim.x + threadIdx.x;
    if (i == 0) g_ticket = 0;
    if (i < N) g_cnt[i] = 0;
    if (i < F * F) {
        float w = W[i];
        __nv_bfloat16 h = __float2bfloat16(w);
        g_whi[i] = h;
        g_wlo[i] = __float2bfloat16(w - __bfloat162float(h));
        float b = B[i];
        h = __float2bfloat16(b);
        g_bhi[i] = h;
        g_blo[i] = __float2bfloat16(b - __bfloat162float(h));
    }
}

// P2: histogram of src
__global__ void p2_hist(const int* __restrict__ ei, int E) {
    int e = blockIdx.x * blockDim.x + threadIdx.x;
    if (e < E) atomicAdd(&g_cnt[ei[e]], 1);
}

// P3: per-block exclusive scan (512 nodes/block), emit block sums
__global__ __launch_bounds__(SCAN_B) void p3_scan(int N) {
    __shared__ int s[SCAN_B];
    int tid = threadIdx.x;
    int i = blockIdx.x * SCAN_B + tid;
    int v = (i < N) ? g_cnt[i] : 0;
    s[tid] = v;
    __syncthreads();
#pragma unroll
    for (int off = 1; off < SCAN_B; off <<= 1) {
        int t = (tid >= off) ? s[tid - off] : 0;
        __syncthreads();
        s[tid] += t;
        __syncthreads();
    }
    if (i < N) g_base[i] = s[tid] - v;          // exclusive within block
    if (tid == SCAN_B - 1) g_bsums[blockIdx.x] = s[tid];
}

// P45: every block redundantly scans the block sums, applies its offset,
// seeds cursors.
__global__ __launch_bounds__(SCAN_B) void p45_offsets(int N, int nb) {
    __shared__ int s[SCAN_B];
    int tid = threadIdx.x;
    int b = blockIdx.x;
    s[tid] = (tid < nb) ? g_bsums[tid] : 0;
    __syncthreads();
#pragma unroll
    for (int off = 1; off < SCAN_B; off <<= 1) {
        int t = (tid >= off) ? s[tid - off] : 0;
        __syncthreads();
        s[tid] += t;
        __syncthreads();
    }
    int offset = (b > 0) ? s[b - 1] : 0;
    int i = b * SCAN_B + tid;
    if (i < N) {
        int v = g_base[i] + offset;
        g_base[i] = v;
        g_cursor[i] = v;
    }
}

// P6: bucket dst indices into CSR order
__global__ void p6_bucket(const int* __restrict__ ei, int E) {
    int e = blockIdx.x * blockDim.x + threadIdx.x;
    if (e < E) {
        int src = ei[e];
        int dst = ei[E + e];
        int pos = atomicAdd(&g_cursor[src], 1);
        g_sorted[pos] = dst;
    }
}

// ---------------------------------------------------------------------------
// K2: PERSISTENT fused GATHER + GEMM.
// Per 128-row tile: 8 warps gather-aggregate 16 nodes each (register acc,
// degree-normalized) straight into smem A planes -> mma(W) -> stage x tile
// -> mma(B) -> store. Gather L2 time overlaps other CTAs' tensor work.
// ---------------------------------------------------------------------------
__device__ __forceinline__ void bsplit(float v, __nv_bfloat16* hi, __nv_bfloat16* lo) {
    __nv_bfloat16 h = __float2bfloat16(v);
    *hi = h;
    *lo = __float2bfloat16(v - __bfloat162float(h));
}

#define MMA_BF16(d, a, b)                                                     \
    asm volatile("mma.sync.aligned.m16n8k16.row.col.f32.bf16.bf16.f32 "       \
                 "{%0,%1,%2,%3}, {%4,%5,%6,%7}, {%8,%9}, {%0,%1,%2,%3};"      \
                 : "+f"((d)[0]), "+f"((d)[1]), "+f"((d)[2]), "+f"((d)[3])     \
                 : "r"((a)[0]), "r"((a)[1]), "r"((a)[2]), "r"((a)[3]),        \
                   "r"((b)[0]), "r"((b)[1]))

__global__ __launch_bounds__(256, 1) void gemm_fused(
        const float* __restrict__ x, float* __restrict__ out,
        int N, int E, int ntiles) {
    extern __shared__ __nv_bfloat16 smem[];
    __nv_bfloat16* sWhi = smem;                       // phase0 weights hi
    __nv_bfloat16* sWlo = sWhi + 128 * SSTRIDE;
    __nv_bfloat16* sBhi = sWlo + 128 * SSTRIDE;       // phase1 weights hi
    __nv_bfloat16* sBlo = sBhi + 128 * SSTRIDE;
    __nv_bfloat16* sAhi = sBlo + 128 * SSTRIDE;       // A tile (reused per phase)
    __nv_bfloat16* sAlo = sAhi + 128 * SSTRIDE;
    __shared__ int s_tile;

    const int tid = threadIdx.x;
    const int lane = tid & 31;
    const int warp = tid >> 5;
    const int wm = warp & 3;    // 4 row groups of 32
    const int wn = warp >> 2;   // 2 col groups of 64
    const int g = lane >> 2;
    const int tg = lane & 3;
    const float4* x4 = reinterpret_cast<const float4*>(x);

    // Stage all 4 weight planes ONCE per CTA.
#pragma unroll 4
    for (int i = tid; i < 128 * 16; i += 256) {
        int r = i >> 4;
        int c8 = (i & 15) << 3;
        *reinterpret_cast<uint4*>(sWhi + r * SSTRIDE + c8) =
            reinterpret_cast<const uint4*>(g_whi)[i];
        *reinterpret_cast<uint4*>(sWlo + r * SSTRIDE + c8) =
            reinterpret_cast<const uint4*>(g_wlo)[i];
        *reinterpret_cast<uint4*>(sBhi + r * SSTRIDE + c8) =
            reinterpret_cast<const uint4*>(g_bhi)[i];
        *reinterpret_cast<uint4*>(sBlo + r * SSTRIDE + c8) =
            reinterpret_cast<const uint4*>(g_blo)[i];
    }

    while (true) {
        __syncthreads();   // prior tile's LDS reads done; s_tile safe
        if (tid == 0) s_tile = atomicAdd(&g_ticket, 1);
        __syncthreads();
        int tile = s_tile;
        if (tile >= ntiles) break;
        int rowBase = tile * GTILE;

        float acc[2][8][4];
#pragma unroll
        for (int a = 0; a < 2; a++)
#pragma unroll
            for (int b = 0; b < 8; b++)
#pragma unroll
                for (int c = 0; c < 4; c++) acc[a][b][c] = 0.f;

        for (int phase = 0; phase < 2; phase++) {
            const __nv_bfloat16* wh = (phase == 0) ? sWhi : sBhi;
            const __nv_bfloat16* wl = (phase == 0) ? sWlo : sBlo;

            if (phase == 0) {
                // Gather-aggregate 16 nodes per warp into sA planes.
                int nodeBase = rowBase + warp * 16;
                for (int t = 0; t < 16; t++) {
                    int n = nodeBase + t;
                    float4 va = make_float4(0.f, 0.f, 0.f, 0.f);
                    int cnt = 0;
                    if (n < N) {
                        int s = g_base[n];
                        int eend = (n + 1 < N) ? g_base[n + 1] : E;
                        cnt = eend - s;
                        const int* sp = g_sorted + s;
                        for (int b = 0; b < cnt; b += 32) {
                            int dv = (b + lane < cnt) ? sp[b + lane] : 0;
                            int m = min(32, cnt - b);
                            int j = 0;
                            for (; j + 4 <= m; j += 4) {
                                int d0 = __shfl_sync(0xffffffffu, dv, j);
                                int d1 = __shfl_sync(0xffffffffu, dv, j + 1);
                                int d2 = __shfl_sync(0xffffffffu, dv, j + 2);
                                int d3 = __shfl_sync(0xffffffffu, dv, j + 3);
                                float4 v0 = x4[(size_t)d0 * 32 + lane];
                                float4 v1 = x4[(size_t)d1 * 32 + lane];
                                float4 v2 = x4[(size_t)d2 * 32 + lane];
                                float4 v3 = x4[(size_t)d3 * 32 + lane];
                                va.x += v0.x; va.y += v0.y; va.z += v0.z; va.w += v0.w;
                                va.x += v1.x; va.y += v1.y; va.z += v1.z; va.w += v1.w;
                                va.x += v2.x; va.y += v2.y; va.z += v2.z; va.w += v2.w;
                                va.x += v3.x; va.y += v3.y; va.z += v3.z; va.w += v3.w;
                            }
                            for (; j < m; j++) {
                                int d = __shfl_sync(0xffffffffu, dv, j);
                                float4 v = x4[(size_t)d * 32 + lane];
                                va.x += v.x; va.y += v.y; va.z += v.z; va.w += v.w;
                            }
                        }
                    }
                    float rd = (cnt > 0) ? (1.0f / (float)cnt) : 1.0f;
                    va.x *= rd; va.y *= rd; va.z *= rd; va.w *= rd;
                    int o = (warp * 16 + t) * SSTRIDE + lane * 4;
                    bsplit(va.x, sAhi + o, sAlo + o);
                    bsplit(va.y, sAhi + o + 1, sAlo + o + 1);
                    bsplit(va.z, sAhi + o + 2, sAlo + o + 2);
                    bsplit(va.w, sAhi + o + 3, sAlo + o + 3);
                }
            } else {
                __syncthreads();   // phase-0 fragment reads done before restage
                // Stage x tile (128 rows), split hi/lo.
#pragma unroll 4
                for (int i = tid; i < GTILE * 32; i += 256) {
                    int r = i >> 5;
                    int c4 = (i & 31) << 2;
                    int gr = rowBase + r;
                    float4 v = make_float4(0.f, 0.f, 0.f, 0.f);
                    if (gr < N)
                        v = x4[(size_t)gr * 32 + (i & 31)];
                    int o = r * SSTRIDE + c4;
                    bsplit(v.x, sAhi + o, sAlo + o);
                    bsplit(v.y, sAhi + o + 1, sAlo + o + 1);
                    bsplit(v.z, sAhi + o + 2, sAlo + o + 2);
                    bsplit(v.w, sAhi + o + 3, sAlo + o + 3);
                }
            }
            __syncthreads();

#pragma unroll
            for (int ks = 0; ks < 8; ks++) {
                const int kc = ks * 16 + tg * 2;
                uint32_t bhi[8][2], blo[8][2];
#pragma unroll
                for (int nt = 0; nt < 8; nt++) {
                    int j0 = wn * 64 + nt * 8 + g;
                    const __nv_bfloat16* p = wh + j0 * SSTRIDE + kc;
                    bhi[nt][0] = *reinterpret_cast<const uint32_t*>(p);
                    bhi[nt][1] = *reinterpret_cast<const uint32_t*>(p + 8);
                    const __nv_bfloat16* q = wl + j0 * SSTRIDE + kc;
                    blo[nt][0] = *reinterpret_cast<const uint32_t*>(q);
                    blo[nt][1] = *reinterpret_cast<const uint32_t*>(q + 8);
                }
#pragma unroll
                for (int mt = 0; mt < 2; mt++) {
                    int r0 = wm * 32 + mt * 16 + g;
                    uint32_t ahi[4], alo[4];
                    const __nv_bfloat16* p0 = sAhi + r0 * SSTRIDE + kc;
                    const __nv_bfloat16* p1 = sAhi + (r0 + 8) * SSTRIDE + kc;
                    ahi[0] = *reinterpret_cast<const uint32_t*>(p0);
                    ahi[1] = *reinterpret_cast<const uint32_t*>(p1);
                    ahi[2] = *reinterpret_cast<const uint32_t*>(p0 + 8);
                    ahi[3] = *reinterpret_cast<const uint32_t*>(p1 + 8);
                    const __nv_bfloat16* q0 = sAlo + r0 * SSTRIDE + kc;
                    const __nv_bfloat16* q1 = sAlo + (r0 + 8) * SSTRIDE + kc;
                    alo[0] = *reinterpret_cast<const uint32_t*>(q0);
                    alo[1] = *reinterpret_cast<const uint32_t*>(q1);
                    alo[2] = *reinterpret_cast<const uint32_t*>(q0 + 8);
                    alo[3] = *reinterpret_cast<const uint32_t*>(q1 + 8);
#pragma unroll
                    for (int nt = 0; nt < 8; nt++) {
                        MMA_BF16(acc[mt][nt], ahi, bhi[nt]);
                        MMA_BF16(acc[mt][nt], ahi, blo[nt]);
                        MMA_BF16(acc[mt][nt], alo, bhi[nt]);
                    }
                }
            }
        }

        // Epilogue
#pragma unroll
        for (int mt = 0; mt < 2; mt++) {
            int r = rowBase + wm * 32 + mt * 16 + g;
#pragma unroll
            for (int nt = 0; nt < 8; nt++) {
                int c = wn * 64 + nt * 8 + tg * 2;
                if (r < N) {
                    float2 v = make_float2(acc[mt][nt][0], acc[mt][nt][1]);
                    *reinterpret_cast<float2*>(out + (size_t)r * F + c) = v;
                }
                if (r + 8 < N) {
                    float2 v = make_float2(acc[mt][nt][2], acc[mt][nt][3]);
                    *reinterpret_cast<float2*>(out + (size_t)(r + 8) * F + c) = v;
                }
            }
        }
    }
}

// ---------------------------------------------------------------------------
extern "C" void kernel_launch(void* const* d_in, const int* in_sizes, int n_in,
                              void* d_out, int out_size) {
    const float* x = (const float*)d_in[0];
    const int* ei = (const int*)d_in[1];     // int32 (JAX x64-disabled)
    const float* W = (const float*)d_in[2];
    const float* B = (const float*)d_in[3];
    float* out = (float*)d_out;

    int N = in_sizes[0] / F;   // 100000
    int E = in_sizes[1] / 2;   // 625000
    if (N > MAX_NODES) N = MAX_NODES;
    if (E > MAX_EDGES) E = MAX_EDGES;

    int nb = (N + SCAN_B - 1) / SCAN_B;      // scan blocks (196)

    p1_zero_conv<<<(N + 255) / 256, 256>>>(W, B, N);
    p2_hist<<<(E + 255) / 256, 256>>>(ei, E);
    p3_scan<<<nb, SCAN_B>>>(N);
    p45_offsets<<<nb, SCAN_B>>>(N, nb);
    p6_bucket<<<(E + 255) / 256, 256>>>(ei, E);

    // smem: 6 planes * 128 rows * SSTRIDE bf16 = 208896 B
    size_t smem = (size_t)6 * 128 * SSTRIDE * sizeof(__nv_bfloat16);
    cudaFuncSetAttribute(gemm_fused, cudaFuncAttributeMaxDynamicSharedMemorySize,
                         (int)smem);
    int ntiles = (N + GTILE - 1) / GTILE;
    gemm_fused<<<152, 256, smem>>>(x, out, N, E, ntiles);
}

// round 12
// speedup vs baseline: 1.5745x; 1.5745x over previous
#include <cuda_runtime.h>
#include <cuda_bf16.h>
#include <cstdint>

#define MAX_NODES 100000
#define MAX_EDGES 625000
#define F 128
#define SSTRIDE 136   // padded bf16 row stride -> conflict-free fragment LDS
#define SCAN_B 512    // nodes per scan block
#define GTILE 128     // rows per tile (persistent loop)

__device__ __align__(16) float g_agg[(size_t)MAX_NODES * F];
__device__ int g_cnt[MAX_NODES];        // zero-init at load; re-zeroed by p45
__device__ int g_base[MAX_NODES];
__device__ int g_cursor[MAX_NODES];
__device__ int g_sorted[MAX_EDGES];
__device__ int g_bsums[256];
__device__ int g_ticket;                // zero-init at load; reset by p45
// pre-split weight planes (hi/lo bf16), filled once per launch
__device__ __align__(16) __nv_bfloat16 g_whi[F * F];
__device__ __align__(16) __nv_bfloat16 g_wlo[F * F];
__device__ __align__(16) __nv_bfloat16 g_bhi[F * F];
__device__ __align__(16) __nv_bfloat16 g_blo[F * F];

// ---------------------------------------------------------------------------
// P1: pre-split W/B into bf16 hi/lo planes (64 blocks only)
// ---------------------------------------------------------------------------
__global__ void p1_conv(const float* __restrict__ W, const float* __restrict__ B) {
    int i = blockIdx.x * blockDim.x + threadIdx.x;
    float w = W[i];
    __nv_bfloat16 h = __float2bfloat16(w);
    g_whi[i] = h;
    g_wlo[i] = __float2bfloat16(w - __bfloat162float(h));
    float b = B[i];
    h = __float2bfloat16(b);
    g_bhi[i] = h;
    g_blo[i] = __float2bfloat16(b - __bfloat162float(h));
}

// P2: histogram of src
__global__ void p2_hist(const int* __restrict__ ei, int E) {
    int e = blockIdx.x * blockDim.x + threadIdx.x;
    if (e < E) atomicAdd(&g_cnt[ei[e]], 1);
}

// P3: per-block exclusive scan via warp shuffles (512 threads, 16 warps)
__global__ __launch_bounds__(SCAN_B) void p3_scan(int N) {
    __shared__ int wsum[16];
    int tid = threadIdx.x;
    int lane = tid & 31;
    int wid = tid >> 5;
    int i = blockIdx.x * SCAN_B + tid;
    int v = (i < N) ? g_cnt[i] : 0;
    int s = v;
#pragma unroll
    for (int off = 1; off < 32; off <<= 1) {
        int t = __shfl_up_sync(0xffffffffu, s, off);
        if (lane >= off) s += t;
    }
    if (lane == 31) wsum[wid] = s;
    __syncthreads();
    if (wid == 0 && lane < 16) {
        int w = wsum[lane];
#pragma unroll
        for (int off = 1; off < 16; off <<= 1) {
            int t = __shfl_up_sync(0x0000ffffu, w, off);
            if (lane >= off) w += t;
        }
        wsum[lane] = w;
    }
    __syncthreads();
    int incl = s + ((wid > 0) ? wsum[wid - 1] : 0);
    if (i < N) g_base[i] = incl - v;            // exclusive within block
    if (tid == SCAN_B - 1) g_bsums[blockIdx.x] = incl;
}

// P45: redundant block-sum scan per block (shuffle-based), apply offset,
// seed cursors, re-zero g_cnt for next replay, reset gemm ticket.
__global__ __launch_bounds__(SCAN_B) void p45_offsets(int N, int nb) {
    __shared__ int wsum[16];
    __shared__ int sc[SCAN_B];
    int tid = threadIdx.x;
    int lane = tid & 31;
    int wid = tid >> 5;
    int b = blockIdx.x;
    if (b == 0 && tid == 0) g_ticket = 0;
    int v = (tid < nb) ? g_bsums[tid] : 0;
    int s = v;
#pragma unroll
    for (int off = 1; off < 32; off <<= 1) {
        int t = __shfl_up_sync(0xffffffffu, s, off);
        if (lane >= off) s += t;
    }
    if (lane == 31) wsum[wid] = s;
    __syncthreads();
    if (wid == 0 && lane < 16) {
        int w = wsum[lane];
#pragma unroll
        for (int off = 1; off < 16; off <<= 1) {
            int t = __shfl_up_sync(0x0000ffffu, w, off);
            if (lane >= off) w += t;
        }
        wsum[lane] = w;
    }
    __syncthreads();
    sc[tid] = s + ((wid > 0) ? wsum[wid - 1] : 0);
    __syncthreads();
    int offset = (b > 0) ? sc[b - 1] : 0;
    int i = b * SCAN_B + tid;
    if (i < N) {
        int val = g_base[i] + offset;
        g_base[i] = val;
        g_cursor[i] = val;
        g_cnt[i] = 0;                 // cnt dead after p3; pre-zero for next replay
    }
}

// P6: bucket dst indices into CSR order
__global__ void p6_bucket(const int* __restrict__ ei, int E) {
    int e = blockIdx.x * blockDim.x + threadIdx.x;
    if (e < E) {
        int src = ei[e];
        int dst = ei[E + e];
        int pos = atomicAdd(&g_cursor[src], 1);
        g_sorted[pos] = dst;
    }
}

// ---------------------------------------------------------------------------
// P7: gather-aggregate. One warp per node, 4-way unrolled gather for MLP.
// (Runs standalone at high occupancy — do NOT fuse into the GEMM; round-10
//  showed a +70us regression from losing latency-hiding warps.)
// ---------------------------------------------------------------------------
__global__ __launch_bounds__(256) void p7_gather(
        const float* __restrict__ x, int N, int E) {
    int n = (blockIdx.x * 256 + threadIdx.x) >> 5;
    int lane = threadIdx.x & 31;
    if (n >= N) return;
    int s = g_base[n];
    int eend = (n + 1 < N) ? g_base[n + 1] : E;
    int cnt = eend - s;
    const float4* x4 = reinterpret_cast<const float4*>(x);
    const int* sp = g_sorted + s;
    float4 acc = make_float4(0.f, 0.f, 0.f, 0.f);
    for (int b = 0; b < cnt; b += 32) {
        int dv = (b + lane < cnt) ? sp[b + lane] : 0;
        int m = min(32, cnt - b);
        int j = 0;
        for (; j + 4 <= m; j += 4) {
            int d0 = __shfl_sync(0xffffffffu, dv, j);
            int d1 = __shfl_sync(0xffffffffu, dv, j + 1);
            int d2 = __shfl_sync(0xffffffffu, dv, j + 2);
            int d3 = __shfl_sync(0xffffffffu, dv, j + 3);
            float4 v0 = x4[(size_t)d0 * 32 + lane];
            float4 v1 = x4[(size_t)d1 * 32 + lane];
            float4 v2 = x4[(size_t)d2 * 32 + lane];
            float4 v3 = x4[(size_t)d3 * 32 + lane];
            acc.x += v0.x; acc.y += v0.y; acc.z += v0.z; acc.w += v0.w;
            acc.x += v1.x; acc.y += v1.y; acc.z += v1.z; acc.w += v1.w;
            acc.x += v2.x; acc.y += v2.y; acc.z += v2.z; acc.w += v2.w;
            acc.x += v3.x; acc.y += v3.y; acc.z += v3.z; acc.w += v3.w;
        }
        for (; j < m; j++) {
            int d = __shfl_sync(0xffffffffu, dv, j);
            float4 v = x4[(size_t)d * 32 + lane];
            acc.x += v.x; acc.y += v.y; acc.z += v.z; acc.w += v.w;
        }
    }
    float rd = (cnt > 0) ? (1.0f / (float)cnt) : 1.0f;
    acc.x *= rd; acc.y *= rd; acc.z *= rd; acc.w *= rd;
    reinterpret_cast<float4*>(g_agg + (size_t)n * F)[lane] = acc;
}

// ---------------------------------------------------------------------------
// K2: PERSISTENT fused GEMM  out = agg @ W^T + x @ B^T  (bf16x3 mma.sync).
// Weights staged once per CTA; dynamic tile ticket; x-tile prefetched into
// registers before the phase-0 MMA loop so its L2 latency hides under MMA.
// ---------------------------------------------------------------------------
__device__ __forceinline__ void bsplit(float v, __nv_bfloat16* hi, __nv_bfloat16* lo) {
    __nv_bfloat16 h = __float2bfloat16(v);
    *hi = h;
    *lo = __float2bfloat16(v - __bfloat162float(h));
}

#define MMA_BF16(d, a, b)                                                     \
    asm volatile("mma.sync.aligned.m16n8k16.row.col.f32.bf16.bf16.f32 "       \
                 "{%0,%1,%2,%3}, {%4,%5,%6,%7}, {%8,%9}, {%0,%1,%2,%3};"      \
                 : "+f"((d)[0]), "+f"((d)[1]), "+f"((d)[2]), "+f"((d)[3])     \
                 : "r"((a)[0]), "r"((a)[1]), "r"((a)[2]), "r"((a)[3]),        \
                   "r"((b)[0]), "r"((b)[1]))

__device__ __forceinline__ void mma_phase(
        const __nv_bfloat16* __restrict__ wh, const __nv_bfloat16* __restrict__ wl,
        const __nv_bfloat16* __restrict__ sAhi, const __nv_bfloat16* __restrict__ sAlo,
        int wm, int wn, int g, int tg, float (&acc)[2][8][4]) {
#pragma unroll
    for (int ks = 0; ks < 8; ks++) {
        const int kc = ks * 16 + tg * 2;
        uint32_t bhi[8][2], blo[8][2];
#pragma unroll
        for (int nt = 0; nt < 8; nt++) {
            int j0 = wn * 64 + nt * 8 + g;
            const __nv_bfloat16* p = wh + j0 * SSTRIDE + kc;
            bhi[nt][0] = *reinterpret_cast<const uint32_t*>(p);
            bhi[nt][1] = *reinterpret_cast<const uint32_t*>(p + 8);
            const __nv_bfloat16* q = wl + j0 * SSTRIDE + kc;
            blo[nt][0] = *reinterpret_cast<const uint32_t*>(q);
            blo[nt][1] = *reinterpret_cast<const uint32_t*>(q + 8);
        }
#pragma unroll
        for (int mt = 0; mt < 2; mt++) {
            int r0 = wm * 32 + mt * 16 + g;
            uint32_t ahi[4], alo[4];
            const __nv_bfloat16* p0 = sAhi + r0 * SSTRIDE + kc;
            const __nv_bfloat16* p1 = sAhi + (r0 + 8) * SSTRIDE + kc;
            ahi[0] = *reinterpret_cast<const uint32_t*>(p0);
            ahi[1] = *reinterpret_cast<const uint32_t*>(p1);
            ahi[2] = *reinterpret_cast<const uint32_t*>(p0 + 8);
            ahi[3] = *reinterpret_cast<const uint32_t*>(p1 + 8);
            const __nv_bfloat16* q0 = sAlo + r0 * SSTRIDE + kc;
            const __nv_bfloat16* q1 = sAlo + (r0 + 8) * SSTRIDE + kc;
            alo[0] = *reinterpret_cast<const uint32_t*>(q0);
            alo[1] = *reinterpret_cast<const uint32_t*>(q1);
            alo[2] = *reinterpret_cast<const uint32_t*>(q0 + 8);
            alo[3] = *reinterpret_cast<const uint32_t*>(q1 + 8);
#pragma unroll
            for (int nt = 0; nt < 8; nt++) {
                MMA_BF16(acc[mt][nt], ahi, bhi[nt]);
                MMA_BF16(acc[mt][nt], ahi, blo[nt]);
                MMA_BF16(acc[mt][nt], alo, bhi[nt]);
            }
        }
    }
}

__global__ __launch_bounds__(256, 1) void gemm_persist(
        const float* __restrict__ x, float* __restrict__ out,
        int N, int ntiles) {
    extern __shared__ __nv_bfloat16 smem[];
    __nv_bfloat16* sWhi = smem;
    __nv_bfloat16* sWlo = sWhi + 128 * SSTRIDE;
    __nv_bfloat16* sBhi = sWlo + 128 * SSTRIDE;
    __nv_bfloat16* sBlo = sBhi + 128 * SSTRIDE;
    __nv_bfloat16* sAhi = sBlo + 128 * SSTRIDE;   // A tile (reused per phase)
    __nv_bfloat16* sAlo = sAhi + 128 * SSTRIDE;
    __shared__ int s_tile;

    const int tid = threadIdx.x;
    const int lane = tid & 31;
    const int warp = tid >> 5;
    const int wm = warp & 3;
    const int wn = warp >> 2;
    const int g = lane >> 2;
    const int tg = lane & 3;
    const float4* x4 = reinterpret_cast<const float4*>(x);

    // Stage all 4 weight planes ONCE per CTA.
#pragma unroll 4
    for (int i = tid; i < 128 * 16; i += 256) {
        int r = i >> 4;
        int c8 = (i & 15) << 3;
        *reinterpret_cast<uint4*>(sWhi + r * SSTRIDE + c8) =
            reinterpret_cast<const uint4*>(g_whi)[i];
        *reinterpret_cast<uint4*>(sWlo + r * SSTRIDE + c8) =
            reinterpret_cast<const uint4*>(g_wlo)[i];
        *reinterpret_cast<uint4*>(sBhi + r * SSTRIDE + c8) =
            reinterpret_cast<const uint4*>(g_bhi)[i];
        *reinterpret_cast<uint4*>(sBlo + r * SSTRIDE + c8) =
            reinterpret_cast<const uint4*>(g_blo)[i];
    }

    while (true) {
        __syncthreads();
        if (tid == 0) s_tile = atomicAdd(&g_ticket, 1);
        __syncthreads();
        int tile = s_tile;
        if (tile >= ntiles) break;
        int rowBase = tile * GTILE;

        float acc[2][8][4];
#pragma unroll
        for (int a = 0; a < 2; a++)
#pragma unroll
            for (int b = 0; b < 8; b++)
#pragma unroll
                for (int c = 0; c < 4; c++) acc[a][b][c] = 0.f;

        // ---- stage agg tile (phase 0 A) ----
#pragma unroll 4
        for (int i = tid; i < GTILE * 32; i += 256) {
            int r = i >> 5;
            int c4 = (i & 31) << 2;
            int gr = rowBase + r;
            float4 v = make_float4(0.f, 0.f, 0.f, 0.f);
            if (gr < N)
                v = reinterpret_cast<const float4*>(g_agg)[(size_t)gr * 32 + (i & 31)];
            int o = r * SSTRIDE + c4;
            bsplit(v.x, sAhi + o, sAlo + o);
            bsplit(v.y, sAhi + o + 1, sAlo + o + 1);
            bsplit(v.z, sAhi + o + 2, sAlo + o + 2);
            bsplit(v.w, sAhi + o + 3, sAlo + o + 3);
        }
        // ---- prefetch x tile into registers (hides under phase-0 MMA) ----
        float4 xr[16];
#pragma unroll
        for (int j = 0; j < 16; j++) {
            int i = tid + j * 256;
            int gr = rowBase + (i >> 5);
            xr[j] = (gr < N) ? x4[(size_t)gr * 32 + (i & 31)]
                             : make_float4(0.f, 0.f, 0.f, 0.f);
        }
        __syncthreads();

        mma_phase(sWhi, sWlo, sAhi, sAlo, wm, wn, g, tg, acc);   // phase 0

        __syncthreads();   // phase-0 fragment reads done before restage
        // ---- convert prefetched x regs into A planes ----
#pragma unroll
        for (int j = 0; j < 16; j++) {
            int i = tid + j * 256;
            int o = (i >> 5) * SSTRIDE + ((i & 31) << 2);
            bsplit(xr[j].x, sAhi + o, sAlo + o);
            bsplit(xr[j].y, sAhi + o + 1, sAlo + o + 1);
            bsplit(xr[j].z, sAhi + o + 2, sAlo + o + 2);
            bsplit(xr[j].w, sAhi + o + 3, sAlo + o + 3);
        }
        __syncthreads();

        mma_phase(sBhi, sBlo, sAhi, sAlo, wm, wn, g, tg, acc);   // phase 1

        // Epilogue
#pragma unroll
        for (int mt = 0; mt < 2; mt++) {
            int r = rowBase + wm * 32 + mt * 16 + g;
#pragma unroll
            for (int nt = 0; nt < 8; nt++) {
                int c = wn * 64 + nt * 8 + tg * 2;
                if (r < N) {
                    float2 v = make_float2(acc[mt][nt][0], acc[mt][nt][1]);
                    *reinterpret_cast<float2*>(out + (size_t)r * F + c) = v;
                }
                if (r + 8 < N) {
                    float2 v = make_float2(acc[mt][nt][2], acc[mt][nt][3]);
                    *reinterpret_cast<float2*>(out + (size_t)(r + 8) * F + c) = v;
                }
            }
        }
    }
}

// ---------------------------------------------------------------------------
extern "C" void kernel_launch(void* const* d_in, const int* in_sizes, int n_in,
                              void* d_out, int out_size) {
    const float* x = (const float*)d_in[0];
    const int* ei = (const int*)d_in[1];     // int32 (JAX x64-disabled)
    const float* W = (const float*)d_in[2];
    const float* B = (const float*)d_in[3];
    float* out = (float*)d_out;

    int N = in_sizes[0] / F;   // 100000
    int E = in_sizes[1] / 2;   // 625000
    if (N > MAX_NODES) N = MAX_NODES;
    if (E > MAX_EDGES) E = MAX_EDGES;

    int nb = (N + SCAN_B - 1) / SCAN_B;      // scan blocks (196)

    p1_conv<<<(F * F) / 256, 256>>>(W, B);
    p2_hist<<<(E + 255) / 256, 256>>>(ei, E);
    p3_scan<<<nb, SCAN_B>>>(N);
    p45_offsets<<<nb, SCAN_B>>>(N, nb);
    p6_bucket<<<(E + 255) / 256, 256>>>(ei, E);
    p7_gather<<<(N * 32 + 255) / 256, 256>>>(x, N, E);

    // smem: 6 planes * 128 rows * SSTRIDE bf16 = 208896 B
    size_t smem = (size_t)6 * 128 * SSTRIDE * sizeof(__nv_bfloat16);
    cudaFuncSetAttribute(gemm_persist, cudaFuncAttributeMaxDynamicSharedMemorySize,
                         (int)smem);
    int ntiles = (N + GTILE - 1) / GTILE;
    gemm_persist<<<152, 256, smem>>>(x, out, N, ntiles);
}